// round 9
// baseline (speedup 1.0000x reference)
#include <cuda_runtime.h>
#include <math.h>

#define NV 35709
#define NF 70789
#define NFP1 (NF + 1)
#define BATCH 32
#define M3 (3 * NV)   // 107127
#define NV3 (NV * 3)

// Output packing: face_color | landmark_p | fst
#define SZ_FC (BATCH * NV * 3)
#define OFF_FC 0
#define OFF_LM (SZ_FC)
#define SZ_LM (BATCH * 68 * 2)
#define OFF_FST (OFF_LM + SZ_LM)

// SH constants
#define C_Y0 0.8862269254527580f
#define C_Y1 1.7724538509055159f
#define C_Y4 2.4270324400f
#define C_Y6 0.7006239800f
#define C_Y8 1.2135162200f

// -------- scratch (device globals; batch-innermost layouts) --------
__device__ float4 g_fs[NV * BATCH];        // [v][b] centered shape
__device__ float4 g_fnorm[NFP1 * BATCH];   // [f][b] face normals (+zero row)
__device__ float  g_tex[M3 * BATCH];       // [row][b] texture
__device__ float  g_rot[BATCH * 9];        // rot = (Rz Ry Rx)^T, row-major
__device__ float  g_mean[3];               // f32 mean (bits load-bearing)
__device__ double g_mean_d[3];

// ---- f32x2 packed helpers (each half is an independent IEEE rn op) ----
__device__ __forceinline__ unsigned long long pack2(float x, float y) {
    unsigned long long r;
    asm("mov.b64 %0, {%1, %2};" : "=l"(r) : "f"(x), "f"(y));
    return r;
}
__device__ __forceinline__ void unpack2(unsigned long long v, float& x, float& y) {
    asm("mov.b64 {%0, %1}, %2;" : "=f"(x), "=f"(y) : "l"(v));
}
__device__ __forceinline__ unsigned long long fma2(
    unsigned long long a, unsigned long long b, unsigned long long c) {
    unsigned long long d;
    asm("fma.rn.f32x2 %0, %1, %2, %3;" : "=l"(d) : "l"(a), "l"(b), "l"(c));
    return d;
}

// ---------------------------------------------------------------------------
// Kernel A: meanshape mean (fp64) + rotations. UNCHANGED from round 8.
// ---------------------------------------------------------------------------
__global__ __launch_bounds__(1024) void setup_kernel(
    const float* __restrict__ coeff, const float* __restrict__ meanshape) {
    __shared__ double sx[1024], sy[1024], sz[1024];
    int t = threadIdx.x;
    double ax = 0.0, ay = 0.0, az = 0.0;
    for (int i = t; i < NV; i += 1024) {
        ax += (double)meanshape[3 * i + 0];
        ay += (double)meanshape[3 * i + 1];
        az += (double)meanshape[3 * i + 2];
    }
    sx[t] = ax; sy[t] = ay; sz[t] = az;
    __syncthreads();
    for (int s = 512; s > 0; s >>= 1) {
        if (t < s) { sx[t] += sx[t + s]; sy[t] += sy[t + s]; sz[t] += sz[t + s]; }
        __syncthreads();
    }
    if (t == 0) {
        g_mean_d[0] = sx[0] / (double)NV;
        g_mean_d[1] = sy[0] / (double)NV;
        g_mean_d[2] = sz[0] / (double)NV;
        g_mean[0] = (float)(sx[0] / (double)NV);
        g_mean[1] = (float)(sy[0] / (double)NV);
        g_mean[2] = (float)(sz[0] / (double)NV);
    }
    if (t < BATCH) {
        const float* c = coeff + t * 277;
        float ax0 = c[244], ay0 = c[245], az0 = c[246];
        float cx = cosf(ax0), sxr = sinf(ax0);
        float cy = cosf(ay0), syr = sinf(ay0);
        float cz = cosf(az0), szr = sinf(az0);
        float Rx[9] = {1, 0, 0,   0, cx, -sxr,   0, sxr, cx};
        float Ry[9] = {cy, 0, syr,   0, 1, 0,   -syr, 0, cy};
        float Rz[9] = {cz, -szr, 0,   szr, cz, 0,   0, 0, 1};
        float Tm[9], R[9];
        #pragma unroll
        for (int i = 0; i < 3; i++)
            #pragma unroll
            for (int j = 0; j < 3; j++) {
                float s = 0.f;
                #pragma unroll
                for (int k = 0; k < 3; k++) s += Rz[i * 3 + k] * Ry[k * 3 + j];
                Tm[i * 3 + j] = s;
            }
        #pragma unroll
        for (int i = 0; i < 3; i++)
            #pragma unroll
            for (int j = 0; j < 3; j++) {
                float s = 0.f;
                #pragma unroll
                for (int k = 0; k < 3; k++) s += Tm[i * 3 + k] * Rx[k * 3 + j];
                R[i * 3 + j] = s;
            }
        #pragma unroll
        for (int i = 0; i < 3; i++)
            #pragma unroll
            for (int j = 0; j < 3; j++)
                g_rot[t * 9 + i * 3 + j] = R[j * 3 + i];
    }
}

// ---------------------------------------------------------------------------
// Kernel B1: fs GEMM. New blocking: 256 rows/CTA, thread = 4 rows x 8 batches
// (4 f32x2 pairs) -> ~1.75 issues per FMA2 (FMA-pipe-bound). Per-element
// k-ascending rn-FMA chains and epilogue order UNCHANGED (bits load-bearing).
// ---------------------------------------------------------------------------
#define TROWS 256
__global__ __launch_bounds__(256) void gemm_fs_kernel(
    const float* __restrict__ idBase, const float* __restrict__ exBase,
    const float* __restrict__ coeff, const float* __restrict__ meanshape) {
    __shared__ __align__(8) float Cs2[144 * 34];   // [k][b], stride 34
    __shared__ float As[TROWS * 17];
    int t = threadIdx.x;
    int i0 = blockIdx.x * TROWS;

    for (int idx = t; idx < BATCH * 144; idx += 256) {
        int b = idx / 144, j = idx - b * 144;
        Cs2[j * 34 + b] = coeff[b * 277 + j];
    }
    __syncthreads();

    int tx = t & 3;        // batch group: batches tx*8 .. tx*8+7 (pairs tx*4..+3)
    int ty = t >> 2;       // row group: rows ty*4 .. ty*4+3
    unsigned long long acc80[4][4], acc64[4][4];
    #pragma unroll
    for (int r = 0; r < 4; r++)
        #pragma unroll
        for (int p = 0; p < 4; p++) { acc80[r][p] = 0ULL; acc64[r][p] = 0ULL; }

    // ---- idBase chunks (K = 0..79, ascending) ----
    for (int k0 = 0; k0 < 80; k0 += 16) {
        #pragma unroll
        for (int j = 0; j < 16; j++) {
            int idx = t + 256 * j;
            int r = idx >> 4, kk = idx & 15;
            int row = i0 + r;
            As[r * 17 + kk] = (row < M3) ? idBase[(size_t)row * 80 + k0 + kk] : 0.f;
        }
        __syncthreads();
        #pragma unroll
        for (int kk = 0; kk < 16; kk++) {
            int k = k0 + kk;
            unsigned long long b0 = *reinterpret_cast<const unsigned long long*>(
                &Cs2[k * 34 + tx * 8 + 0]);
            unsigned long long b1 = *reinterpret_cast<const unsigned long long*>(
                &Cs2[k * 34 + tx * 8 + 2]);
            unsigned long long b2 = *reinterpret_cast<const unsigned long long*>(
                &Cs2[k * 34 + tx * 8 + 4]);
            unsigned long long b3 = *reinterpret_cast<const unsigned long long*>(
                &Cs2[k * 34 + tx * 8 + 6]);
            #pragma unroll
            for (int r = 0; r < 4; r++) {
                float a = As[(ty * 4 + r) * 17 + kk];
                unsigned long long pa = pack2(a, a);
                acc80[r][0] = fma2(pa, b0, acc80[r][0]);
                acc80[r][1] = fma2(pa, b1, acc80[r][1]);
                acc80[r][2] = fma2(pa, b2, acc80[r][2]);
                acc80[r][3] = fma2(pa, b3, acc80[r][3]);
            }
        }
        __syncthreads();
    }
    // ---- exBase chunks (K = 80..143, ascending) ----
    for (int k0 = 80; k0 < 144; k0 += 16) {
        #pragma unroll
        for (int j = 0; j < 16; j++) {
            int idx = t + 256 * j;
            int r = idx >> 4, kk = idx & 15;
            int row = i0 + r;
            As[r * 17 + kk] = (row < M3) ? exBase[(size_t)row * 64 + (k0 - 80) + kk] : 0.f;
        }
        __syncthreads();
        #pragma unroll
        for (int kk = 0; kk < 16; kk++) {
            int k = k0 + kk;
            unsigned long long b0 = *reinterpret_cast<const unsigned long long*>(
                &Cs2[k * 34 + tx * 8 + 0]);
            unsigned long long b1 = *reinterpret_cast<const unsigned long long*>(
                &Cs2[k * 34 + tx * 8 + 2]);
            unsigned long long b2 = *reinterpret_cast<const unsigned long long*>(
                &Cs2[k * 34 + tx * 8 + 4]);
            unsigned long long b3 = *reinterpret_cast<const unsigned long long*>(
                &Cs2[k * 34 + tx * 8 + 6]);
            #pragma unroll
            for (int r = 0; r < 4; r++) {
                float a = As[(ty * 4 + r) * 17 + kk];
                unsigned long long pa = pack2(a, a);
                acc64[r][0] = fma2(pa, b0, acc64[r][0]);
                acc64[r][1] = fma2(pa, b1, acc64[r][1]);
                acc64[r][2] = fma2(pa, b2, acc64[r][2]);
                acc64[r][3] = fma2(pa, b3, acc64[r][3]);
            }
        }
        __syncthreads();
    }

    float* fsf = (float*)g_fs;
    #pragma unroll
    for (int r = 0; r < 4; r++) {
        int row = i0 + ty * 4 + r;
        if (row >= M3) continue;
        int v = row / 3;
        int c = row - 3 * v;
        float ms = meanshape[row];
        float mn = g_mean[c];
        #pragma unroll
        for (int p = 0; p < 4; p++) {
            float lo80, hi80, lo64, hi64;
            unpack2(acc80[r][p], lo80, hi80);
            unpack2(acc64[r][p], lo64, hi64);
            int b = tx * 8 + 2 * p;
            float s0 = __fadd_rn(__fadd_rn(lo80, lo64), ms);
            fsf[((size_t)v * BATCH + b) * 4 + c] = __fsub_rn(s0, mn);
            float s1 = __fadd_rn(__fadd_rn(hi80, hi64), ms);
            fsf[((size_t)v * BATCH + b + 1) * 4 + c] = __fsub_rn(s1, mn);
        }
    }
}

// ---------------------------------------------------------------------------
// Kernel B2: tex GEMM, same new blocking -> g_tex [row][b]
// ---------------------------------------------------------------------------
__global__ __launch_bounds__(256) void gemm_tex_kernel(
    const float* __restrict__ texBase, const float* __restrict__ coeff,
    const float* __restrict__ meantex) {
    __shared__ __align__(8) float Cs2[112 * 34];
    __shared__ float As[TROWS * 17];
    int t = threadIdx.x;
    int i0 = blockIdx.x * TROWS;

    for (int idx = t; idx < BATCH * 112; idx += 256) {
        int b = idx / 112, j = idx - b * 112;
        Cs2[j * 34 + b] = (j < 100) ? coeff[b * 277 + 144 + j] : 0.f;
    }
    __syncthreads();

    int tx = t & 3;
    int ty = t >> 2;
    unsigned long long acc[4][4];
    #pragma unroll
    for (int r = 0; r < 4; r++)
        #pragma unroll
        for (int p = 0; p < 4; p++) acc[r][p] = 0ULL;

    for (int k0 = 0; k0 < 112; k0 += 16) {
        #pragma unroll
        for (int j = 0; j < 16; j++) {
            int idx = t + 256 * j;
            int r = idx >> 4, kk = idx & 15;
            int row = i0 + r;
            int k = k0 + kk;
            As[r * 17 + kk] = (row < M3 && k < 100) ? texBase[(size_t)row * 100 + k] : 0.f;
        }
        __syncthreads();
        #pragma unroll
        for (int kk = 0; kk < 16; kk++) {
            int k = k0 + kk;
            unsigned long long b0 = *reinterpret_cast<const unsigned long long*>(
                &Cs2[k * 34 + tx * 8 + 0]);
            unsigned long long b1 = *reinterpret_cast<const unsigned long long*>(
                &Cs2[k * 34 + tx * 8 + 2]);
            unsigned long long b2 = *reinterpret_cast<const unsigned long long*>(
                &Cs2[k * 34 + tx * 8 + 4]);
            unsigned long long b3 = *reinterpret_cast<const unsigned long long*>(
                &Cs2[k * 34 + tx * 8 + 6]);
            #pragma unroll
            for (int r = 0; r < 4; r++) {
                float a = As[(ty * 4 + r) * 17 + kk];
                unsigned long long pa = pack2(a, a);
                acc[r][0] = fma2(pa, b0, acc[r][0]);
                acc[r][1] = fma2(pa, b1, acc[r][1]);
                acc[r][2] = fma2(pa, b2, acc[r][2]);
                acc[r][3] = fma2(pa, b3, acc[r][3]);
            }
        }
        __syncthreads();
    }

    #pragma unroll
    for (int r = 0; r < 4; r++) {
        int row = i0 + ty * 4 + r;
        if (row >= M3) continue;
        float mt = meantex[row];
        #pragma unroll
        for (int p = 0; p < 4; p++) {
            float lo, hi;
            unpack2(acc[r][p], lo, hi);
            int b = tx * 8 + 2 * p;
            g_tex[(size_t)row * BATCH + b] = lo + mt;
            g_tex[(size_t)row * BATCH + b + 1] = hi + mt;
        }
    }
}

// ---------------------------------------------------------------------------
// Kernel C: face normals — warp per 2 faces. UNCHANGED from round 8
// (14.7us, latency-limited near floor; lhs-fuse cross is load-bearing).
// ---------------------------------------------------------------------------
__global__ __launch_bounds__(256) void facenorm_kernel(const int* __restrict__ face_buf) {
    int w = threadIdx.x >> 5;
    int lane = threadIdx.x & 31;
    int fbase = (blockIdx.x * 8 + w) * 2;
    #pragma unroll
    for (int u = 0; u < 2; u++) {
        int f = fbase + u;
        if (f > NF) continue;
        float4* dst = g_fnorm + (size_t)f * BATCH + lane;
        if (f == NF) { *dst = make_float4(0.f, 0.f, 0.f, 0.f); continue; }
        int i1 = face_buf[f * 3 + 0];
        int i2 = face_buf[f * 3 + 1];
        int i3 = face_buf[f * 3 + 2];
        float4 p1 = g_fs[(size_t)i1 * BATCH + lane];
        float4 p2 = g_fs[(size_t)i2 * BATCH + lane];
        float4 p3 = g_fs[(size_t)i3 * BATCH + lane];
        float e1x = __fsub_rn(p1.x, p2.x), e1y = __fsub_rn(p1.y, p2.y), e1z = __fsub_rn(p1.z, p2.z);
        float e2x = __fsub_rn(p2.x, p3.x), e2y = __fsub_rn(p2.y, p3.y), e2z = __fsub_rn(p2.z, p3.z);
        float cx = __fmaf_rn(e1y, e2z, -__fmul_rn(e1z, e2y));
        float cy = __fmaf_rn(e1z, e2x, -__fmul_rn(e1x, e2z));
        float cz = __fmaf_rn(e1x, e2y, -__fmul_rn(e1y, e2x));
        float n2 = __fadd_rn(__fadd_rn(__fmul_rn(cx, cx), __fmul_rn(cy, cy)), __fmul_rn(cz, cz));
        float len = sqrtf(n2);
        float d = fmaxf(len, 1e-12f);
        *dst = make_float4(__fdiv_rn(cx, d), __fdiv_rn(cy, d), __fdiv_rn(cz, d), 0.f);
    }
}

// ---------------------------------------------------------------------------
// Kernel D: vertex pass — 32 vertices per block (warp loops 4), amortizing
// the per-block constant staging 4x and cutting block count 4x.
// Per-element arithmetic identical.
// ---------------------------------------------------------------------------
__global__ __launch_bounds__(256) void vertex_kernel(
    const int* __restrict__ point_buf, const float* __restrict__ coeff,
    float* __restrict__ out) {
    __shared__ float srot[BATCH * 9];
    __shared__ float strans[BATCH * 3];
    __shared__ float sgsh[BATCH * 27];
    __shared__ float sfc[32 * BATCH * 3];
    __shared__ float sfst[32 * BATCH * 3];

    int t = threadIdx.x;
    for (int idx = t; idx < BATCH * 9; idx += 256) srot[idx] = g_rot[idx];
    for (int idx = t; idx < BATCH * 3; idx += 256)
        strans[idx] = coeff[(idx / 3) * 277 + 274 + (idx % 3)];
    for (int idx = t; idx < BATCH * 27; idx += 256) {
        int b = idx / 27, j = idx - b * 27;
        sgsh[idx] = coeff[b * 277 + 247 + j] + (((j % 9) == 0) ? 0.8f : 0.f);
    }
    __syncthreads();

    int w = t >> 5;
    int lane = t & 31;
    const float* rot = srot + lane * 9;
    const float* gsh = sgsh + lane * 27;
    const float* tr = strans + lane * 3;

    #pragma unroll
    for (int i = 0; i < 4; i++) {
        int vv = w * 4 + i;                // 0..31 within block
        int v = blockIdx.x * 32 + vv;
        if (v >= NV) break;

        const int4* pb = (const int4*)point_buf;
        int4 q0 = pb[(size_t)v * 2 + 0];
        int4 q1 = pb[(size_t)v * 2 + 1];
        const float4* fn = g_fnorm;
        float nx = 0.f, ny = 0.f, nz = 0.f;
        float4 a;
        a = fn[(size_t)q0.x * BATCH + lane]; nx += a.x; ny += a.y; nz += a.z;
        a = fn[(size_t)q0.y * BATCH + lane]; nx += a.x; ny += a.y; nz += a.z;
        a = fn[(size_t)q0.z * BATCH + lane]; nx += a.x; ny += a.y; nz += a.z;
        a = fn[(size_t)q0.w * BATCH + lane]; nx += a.x; ny += a.y; nz += a.z;
        a = fn[(size_t)q1.x * BATCH + lane]; nx += a.x; ny += a.y; nz += a.z;
        a = fn[(size_t)q1.y * BATCH + lane]; nx += a.x; ny += a.y; nz += a.z;
        a = fn[(size_t)q1.z * BATCH + lane]; nx += a.x; ny += a.y; nz += a.z;
        a = fn[(size_t)q1.w * BATCH + lane]; nx += a.x; ny += a.y; nz += a.z;

        float len = sqrtf(nx * nx + ny * ny + nz * nz);
        float inv = 1.f / fmaxf(len, 1e-12f);
        nx *= inv; ny *= inv; nz *= inv;

        float rx = nx * rot[0] + ny * rot[3] + nz * rot[6];
        float ry = nx * rot[1] + ny * rot[4] + nz * rot[7];
        float rz = nx * rot[2] + ny * rot[5] + nz * rot[8];

        float Y[9];
        Y[0] = C_Y0;
        Y[1] = -C_Y1 * ry;
        Y[2] = C_Y1 * rz;
        Y[3] = -C_Y1 * rx;
        Y[4] = C_Y4 * rx * ry;
        Y[5] = -C_Y4 * ry * rz;
        Y[6] = C_Y6 * (3.f * rz * rz - 1.f);
        Y[7] = -C_Y4 * rx * rz;
        Y[8] = C_Y8 * (rx * rx - ry * ry);

        float lit[3];
        #pragma unroll
        for (int c = 0; c < 3; c++) {
            float s = 0.f;
            #pragma unroll
            for (int k = 0; k < 9; k++) s += Y[k] * gsh[c * 9 + k];
            lit[c] = s;
        }

        const float* texv = g_tex + (size_t)v * 3 * BATCH;
        float* fc = sfc + (vv * BATCH + lane) * 3;
        fc[0] = texv[0 * BATCH + lane] * lit[0];
        fc[1] = texv[1 * BATCH + lane] * lit[1];
        fc[2] = texv[2 * BATCH + lane] * lit[2];

        float4 fs4 = g_fs[(size_t)v * BATCH + lane];
        float* fo = sfst + (vv * BATCH + lane) * 3;
        fo[0] = fs4.x * rot[0] + fs4.y * rot[3] + fs4.z * rot[6] + tr[0];
        fo[1] = fs4.x * rot[1] + fs4.y * rot[4] + fs4.z * rot[7] + tr[1];
        fo[2] = fs4.x * rot[2] + fs4.y * rot[5] + fs4.z * rot[8] + tr[2];
    }
    __syncthreads();

    // Write phase: batch b = t>>3; segment seg = t&7 covers 12 consecutive
    // floats of that batch's 96-float (32 verts x 3) span. Fully coalesced.
    size_t v0 = (size_t)blockIdx.x * 32;
    int b = t >> 3;
    int seg = t & 7;
    #pragma unroll
    for (int j = 0; j < 12; j++) {
        int kk = seg * 12 + j;     // 0..95
        int vv = kk / 3;
        int c = kk - vv * 3;
        if (v0 + vv < NV) {
            size_t go = (size_t)b * NV3 + (v0 + vv) * 3 + c;
            out[OFF_FC + go] = sfc[(vv * BATCH + b) * 3 + c];
            out[OFF_FST + go] = sfst[(vv * BATCH + b) * 3 + c];
        }
    }
}

// ---------------------------------------------------------------------------
// Kernel E: landmarks in fp64 from raw inputs. UNCHANGED.
// ---------------------------------------------------------------------------
__global__ __launch_bounds__(128) void landmark_kernel(
    const float* __restrict__ idBase, const float* __restrict__ exBase,
    const float* __restrict__ meanshape, const float* __restrict__ coeff,
    const int* __restrict__ keypoints, float* __restrict__ out) {
    int idx = blockIdx.x * 128 + threadIdx.x;
    if (idx >= BATCH * 68) return;
    int b = idx / 68, l = idx - b * 68;
    int v = keypoints[l];
    const float* c = coeff + b * 277;

    double fs[3];
    #pragma unroll
    for (int cc = 0; cc < 3; cc++) {
        int row = 3 * v + cc;
        const float* idr = idBase + (size_t)row * 80;
        const float* exr = exBase + (size_t)row * 64;
        double s = 0.0;
        for (int k = 0; k < 80; k++) s += (double)idr[k] * (double)c[k];
        for (int k = 0; k < 64; k++) s += (double)exr[k] * (double)c[80 + k];
        fs[cc] = s + (double)meanshape[row] - g_mean_d[cc];
    }

    double ax0 = (double)c[244], ay0 = (double)c[245], az0 = (double)c[246];
    double cx = cos(ax0), sx = sin(ax0);
    double cy = cos(ay0), sy = sin(ay0);
    double cz = cos(az0), sz = sin(az0);
    double R[3][3];
    R[0][0] = cz * cy;  R[0][1] = cz * sy * sx - sz * cx;  R[0][2] = cz * sy * cx + sz * sx;
    R[1][0] = sz * cy;  R[1][1] = sz * sy * sx + cz * cx;  R[1][2] = sz * sy * cx - cz * sx;
    R[2][0] = -sy;      R[2][1] = cy * sx;                 R[2][2] = cy * cx;
    double fst[3];
    #pragma unroll
    for (int j = 0; j < 3; j++)
        fst[j] = fs[0] * R[j][0] + fs[1] * R[j][1] + fs[2] * R[j][2]
               + (double)c[274 + j];

    double Zc = 10.0 - fst[2];
    double lx = (1015.0 * fst[0] + 112.0 * Zc) / Zc;
    double ly = (1015.0 * fst[1] + 112.0 * Zc) / Zc;
    out[OFF_LM + (size_t)idx * 2 + 0] = (float)lx;
    out[OFF_LM + (size_t)idx * 2 + 1] = (float)ly;
}

// ---------------------------------------------------------------------------
// Launcher: fork-join stream overlap (unchanged topology from round 8).
// ---------------------------------------------------------------------------
extern "C" void kernel_launch(void* const* d_in, const int* in_sizes, int n_in,
                              void* d_out, int out_size) {
    const float* coeff     = (const float*)d_in[0];
    const float* idBase    = (const float*)d_in[1];
    const float* exBase    = (const float*)d_in[2];
    const float* texBase   = (const float*)d_in[3];
    const float* meanshape = (const float*)d_in[4];
    const float* meantex   = (const float*)d_in[5];
    const int*   face_buf  = (const int*)d_in[6];
    const int*   point_buf = (const int*)d_in[7];
    const int*   keypoints = (const int*)d_in[8];
    float* out = (float*)d_out;

    static cudaStream_t s2 = 0, s3 = 0;
    static cudaEvent_t evO = 0, evS = 0, evT = 0, evL = 0;
    if (!s2) {
        cudaStreamCreateWithFlags(&s2, cudaStreamNonBlocking);
        cudaStreamCreateWithFlags(&s3, cudaStreamNonBlocking);
        cudaEventCreateWithFlags(&evO, cudaEventDisableTiming);
        cudaEventCreateWithFlags(&evS, cudaEventDisableTiming);
        cudaEventCreateWithFlags(&evT, cudaEventDisableTiming);
        cudaEventCreateWithFlags(&evL, cudaEventDisableTiming);
    }

    int gemm_blocks = (M3 + TROWS - 1) / TROWS;

    cudaEventRecord(evO, 0);
    cudaStreamWaitEvent(s2, evO, 0);
    cudaStreamWaitEvent(s3, evO, 0);

    gemm_tex_kernel<<<gemm_blocks, 256, 0, s2>>>(texBase, coeff, meantex);
    cudaEventRecord(evT, s2);

    setup_kernel<<<1, 1024>>>(coeff, meanshape);
    cudaEventRecord(evS, 0);
    gemm_fs_kernel<<<gemm_blocks, 256>>>(idBase, exBase, coeff, meanshape);
    facenorm_kernel<<<(NFP1 + 15) / 16, 256>>>(face_buf);

    cudaStreamWaitEvent(s3, evS, 0);
    landmark_kernel<<<(BATCH * 68 + 127) / 128, 128, 0, s3>>>(
        idBase, exBase, meanshape, coeff, keypoints, out);
    cudaEventRecord(evL, s3);

    cudaStreamWaitEvent(0, evT, 0);
    vertex_kernel<<<(NV + 31) / 32, 256>>>(point_buf, coeff, out);
    cudaStreamWaitEvent(0, evL, 0);
}

// round 10
// speedup vs baseline: 1.2099x; 1.2099x over previous
#include <cuda_runtime.h>
#include <math.h>

#define NV 35709
#define NF 70789
#define NFP1 (NF + 1)
#define BATCH 32
#define M3 (3 * NV)   // 107127
#define NV3 (NV * 3)

// Output packing: face_color | landmark_p | fst
#define SZ_FC (BATCH * NV * 3)
#define OFF_FC 0
#define OFF_LM (SZ_FC)
#define SZ_LM (BATCH * 68 * 2)
#define OFF_FST (OFF_LM + SZ_LM)

// SH constants
#define C_Y0 0.8862269254527580f
#define C_Y1 1.7724538509055159f
#define C_Y4 2.4270324400f
#define C_Y6 0.7006239800f
#define C_Y8 1.2135162200f

// -------- scratch (device globals; batch-innermost layouts) --------
__device__ float4 g_fs[NV * BATCH];        // [v][b] centered shape
__device__ float4 g_fnorm[NFP1 * BATCH];   // [f][b] face normals (+zero row)
__device__ float  g_tex[M3 * BATCH];       // [row][b] texture
__device__ float  g_rot[BATCH * 9];        // rot = (Rz Ry Rx)^T, row-major
__device__ float  g_mean[3];               // f32 mean (bits load-bearing)
__device__ double g_mean_d[3];

// ---- f32x2 packed helpers (each half is an independent IEEE rn op) ----
__device__ __forceinline__ unsigned long long pack2(float x, float y) {
    unsigned long long r;
    asm("mov.b64 %0, {%1, %2};" : "=l"(r) : "f"(x), "f"(y));
    return r;
}
__device__ __forceinline__ void unpack2(unsigned long long v, float& x, float& y) {
    asm("mov.b64 {%0, %1}, %2;" : "=f"(x), "=f"(y) : "l"(v));
}
__device__ __forceinline__ unsigned long long fma2(
    unsigned long long a, unsigned long long b, unsigned long long c) {
    unsigned long long d;
    asm("fma.rn.f32x2 %0, %1, %2, %3;" : "=l"(d) : "l"(a), "l"(b), "l"(c));
    return d;
}

// ---------------------------------------------------------------------------
// Kernel A: meanshape mean (fp64) + rotations. UNCHANGED.
// ---------------------------------------------------------------------------
__global__ __launch_bounds__(1024) void setup_kernel(
    const float* __restrict__ coeff, const float* __restrict__ meanshape) {
    __shared__ double sx[1024], sy[1024], sz[1024];
    int t = threadIdx.x;
    double ax = 0.0, ay = 0.0, az = 0.0;
    for (int i = t; i < NV; i += 1024) {
        ax += (double)meanshape[3 * i + 0];
        ay += (double)meanshape[3 * i + 1];
        az += (double)meanshape[3 * i + 2];
    }
    sx[t] = ax; sy[t] = ay; sz[t] = az;
    __syncthreads();
    for (int s = 512; s > 0; s >>= 1) {
        if (t < s) { sx[t] += sx[t + s]; sy[t] += sy[t + s]; sz[t] += sz[t + s]; }
        __syncthreads();
    }
    if (t == 0) {
        g_mean_d[0] = sx[0] / (double)NV;
        g_mean_d[1] = sy[0] / (double)NV;
        g_mean_d[2] = sz[0] / (double)NV;
        g_mean[0] = (float)(sx[0] / (double)NV);
        g_mean[1] = (float)(sy[0] / (double)NV);
        g_mean[2] = (float)(sz[0] / (double)NV);
    }
    if (t < BATCH) {
        const float* c = coeff + t * 277;
        float ax0 = c[244], ay0 = c[245], az0 = c[246];
        float cx = cosf(ax0), sxr = sinf(ax0);
        float cy = cosf(ay0), syr = sinf(ay0);
        float cz = cosf(az0), szr = sinf(az0);
        float Rx[9] = {1, 0, 0,   0, cx, -sxr,   0, sxr, cx};
        float Ry[9] = {cy, 0, syr,   0, 1, 0,   -syr, 0, cy};
        float Rz[9] = {cz, -szr, 0,   szr, cz, 0,   0, 0, 1};
        float Tm[9], R[9];
        #pragma unroll
        for (int i = 0; i < 3; i++)
            #pragma unroll
            for (int j = 0; j < 3; j++) {
                float s = 0.f;
                #pragma unroll
                for (int k = 0; k < 3; k++) s += Rz[i * 3 + k] * Ry[k * 3 + j];
                Tm[i * 3 + j] = s;
            }
        #pragma unroll
        for (int i = 0; i < 3; i++)
            #pragma unroll
            for (int j = 0; j < 3; j++) {
                float s = 0.f;
                #pragma unroll
                for (int k = 0; k < 3; k++) s += Tm[i * 3 + k] * Rx[k * 3 + j];
                R[i * 3 + j] = s;
            }
        #pragma unroll
        for (int i = 0; i < 3; i++)
            #pragma unroll
            for (int j = 0; j < 3; j++)
                g_rot[t * 9 + i * 3 + j] = R[j * 3 + i];
    }
}

// ---------------------------------------------------------------------------
// Kernel B1: fs GEMM — round-8 blocking (128 rows, 4 rows x 4 batches/thread)
// + DOUBLE-BUFFERED A staging: next chunk's global loads issue before the
// current chunk's compute, hiding staging latency. Per-element k-ascending
// rn-FMA chains and epilogue order UNCHANGED (bits load-bearing).
// ---------------------------------------------------------------------------
__global__ __launch_bounds__(256) void gemm_fs_kernel(
    const float* __restrict__ idBase, const float* __restrict__ exBase,
    const float* __restrict__ coeff, const float* __restrict__ meanshape) {
    __shared__ __align__(8) float Cs2[144 * 34];   // [k][b]
    __shared__ float As[2][128 * 17];
    int t = threadIdx.x;
    int i0 = blockIdx.x * 128;

    for (int idx = t; idx < BATCH * 144; idx += 256) {
        int b = idx / 144, j = idx - b * 144;
        Cs2[j * 34 + b] = coeff[b * 277 + j];
    }

    int tx = t & 7;        // batches 4tx..4tx+3 (2 pairs)
    int ty = t >> 3;       // rows ty*4..ty*4+3
    unsigned long long acc80[4][2], acc64[4][2];
    #pragma unroll
    for (int r = 0; r < 4; r++)
        #pragma unroll
        for (int p = 0; p < 2; p++) { acc80[r][p] = 0ULL; acc64[r][p] = 0ULL; }

    int sr = t >> 4;           // staging row this thread covers (+256/16 steps)
    int sk = t & 15;           // staging k within chunk

    // prologue: stage chunk 0 (idBase, k=0..15)
    float rg[8];
    #pragma unroll
    for (int j = 0; j < 8; j++) {
        int row = i0 + sr + j * 16;
        rg[j] = (row < M3) ? idBase[(size_t)row * 80 + sk] : 0.f;
    }
    #pragma unroll
    for (int j = 0; j < 8; j++) As[0][(sr + j * 16) * 17 + sk] = rg[j];
    __syncthreads();

    // 9 chunks: ci 0..4 -> idBase (acc80), ci 5..8 -> exBase (acc64)
    #pragma unroll
    for (int ci = 0; ci < 9; ci++) {
        // issue next chunk's global loads (latency overlapped with compute)
        if (ci < 8) {
            int cn = ci + 1;
            const float* Ap = (cn < 5) ? idBase : exBase;
            int ld = (cn < 5) ? 80 : 64;
            int kb = (cn < 5) ? cn * 16 : (cn - 5) * 16;
            #pragma unroll
            for (int j = 0; j < 8; j++) {
                int row = i0 + sr + j * 16;
                rg[j] = (row < M3) ? Ap[(size_t)row * ld + kb + sk] : 0.f;
            }
        }
        // compute current chunk
        const float* buf = As[ci & 1];
        int k0 = ci * 16;
        #pragma unroll
        for (int kk = 0; kk < 16; kk++) {
            int k = k0 + kk;
            float a0 = buf[(ty * 4 + 0) * 17 + kk];
            float a1 = buf[(ty * 4 + 1) * 17 + kk];
            float a2 = buf[(ty * 4 + 2) * 17 + kk];
            float a3 = buf[(ty * 4 + 3) * 17 + kk];
            unsigned long long pa0 = pack2(a0, a0), pa1 = pack2(a1, a1);
            unsigned long long pa2 = pack2(a2, a2), pa3 = pack2(a3, a3);
            unsigned long long b01 = *reinterpret_cast<const unsigned long long*>(
                &Cs2[k * 34 + tx * 4]);
            unsigned long long b23 = *reinterpret_cast<const unsigned long long*>(
                &Cs2[k * 34 + tx * 4 + 2]);
            if (ci < 5) {
                acc80[0][0] = fma2(pa0, b01, acc80[0][0]); acc80[0][1] = fma2(pa0, b23, acc80[0][1]);
                acc80[1][0] = fma2(pa1, b01, acc80[1][0]); acc80[1][1] = fma2(pa1, b23, acc80[1][1]);
                acc80[2][0] = fma2(pa2, b01, acc80[2][0]); acc80[2][1] = fma2(pa2, b23, acc80[2][1]);
                acc80[3][0] = fma2(pa3, b01, acc80[3][0]); acc80[3][1] = fma2(pa3, b23, acc80[3][1]);
            } else {
                acc64[0][0] = fma2(pa0, b01, acc64[0][0]); acc64[0][1] = fma2(pa0, b23, acc64[0][1]);
                acc64[1][0] = fma2(pa1, b01, acc64[1][0]); acc64[1][1] = fma2(pa1, b23, acc64[1][1]);
                acc64[2][0] = fma2(pa2, b01, acc64[2][0]); acc64[2][1] = fma2(pa2, b23, acc64[2][1]);
                acc64[3][0] = fma2(pa3, b01, acc64[3][0]); acc64[3][1] = fma2(pa3, b23, acc64[3][1]);
            }
        }
        // publish next chunk
        if (ci < 8) {
            #pragma unroll
            for (int j = 0; j < 8; j++) As[(ci + 1) & 1][(sr + j * 16) * 17 + sk] = rg[j];
            __syncthreads();
        }
    }

    float* fsf = (float*)g_fs;
    #pragma unroll
    for (int r = 0; r < 4; r++) {
        int row = i0 + ty * 4 + r;
        if (row >= M3) continue;
        int v = row / 3;
        int c = row - 3 * v;
        float ms = meanshape[row];
        float mn = g_mean[c];
        #pragma unroll
        for (int p = 0; p < 2; p++) {
            float lo80, hi80, lo64, hi64;
            unpack2(acc80[r][p], lo80, hi80);
            unpack2(acc64[r][p], lo64, hi64);
            int b = tx * 4 + 2 * p;
            float s0 = __fadd_rn(__fadd_rn(lo80, lo64), ms);
            fsf[((size_t)v * BATCH + b) * 4 + c] = __fsub_rn(s0, mn);
            float s1 = __fadd_rn(__fadd_rn(hi80, hi64), ms);
            fsf[((size_t)v * BATCH + b + 1) * 4 + c] = __fsub_rn(s1, mn);
        }
    }
}

// ---------------------------------------------------------------------------
// Kernel B2: tex GEMM — same double-buffered scheme (7 chunks) -> g_tex
// ---------------------------------------------------------------------------
__global__ __launch_bounds__(256) void gemm_tex_kernel(
    const float* __restrict__ texBase, const float* __restrict__ coeff,
    const float* __restrict__ meantex) {
    __shared__ __align__(8) float Cs2[112 * 34];
    __shared__ float As[2][128 * 17];
    int t = threadIdx.x;
    int i0 = blockIdx.x * 128;

    for (int idx = t; idx < BATCH * 112; idx += 256) {
        int b = idx / 112, j = idx - b * 112;
        Cs2[j * 34 + b] = (j < 100) ? coeff[b * 277 + 144 + j] : 0.f;
    }

    int tx = t & 7;
    int ty = t >> 3;
    unsigned long long acc[4][2];
    #pragma unroll
    for (int r = 0; r < 4; r++)
        #pragma unroll
        for (int p = 0; p < 2; p++) acc[r][p] = 0ULL;

    int sr = t >> 4;
    int sk = t & 15;

    float rg[8];
    #pragma unroll
    for (int j = 0; j < 8; j++) {
        int row = i0 + sr + j * 16;
        rg[j] = (row < M3 && sk < 100) ? texBase[(size_t)row * 100 + sk] : 0.f;
    }
    #pragma unroll
    for (int j = 0; j < 8; j++) As[0][(sr + j * 16) * 17 + sk] = rg[j];
    __syncthreads();

    #pragma unroll
    for (int ci = 0; ci < 7; ci++) {
        if (ci < 6) {
            int kb = (ci + 1) * 16;
            #pragma unroll
            for (int j = 0; j < 8; j++) {
                int row = i0 + sr + j * 16;
                int k = kb + sk;
                rg[j] = (row < M3 && k < 100) ? texBase[(size_t)row * 100 + k] : 0.f;
            }
        }
        const float* buf = As[ci & 1];
        int k0 = ci * 16;
        #pragma unroll
        for (int kk = 0; kk < 16; kk++) {
            int k = k0 + kk;
            float a0 = buf[(ty * 4 + 0) * 17 + kk];
            float a1 = buf[(ty * 4 + 1) * 17 + kk];
            float a2 = buf[(ty * 4 + 2) * 17 + kk];
            float a3 = buf[(ty * 4 + 3) * 17 + kk];
            unsigned long long pa0 = pack2(a0, a0), pa1 = pack2(a1, a1);
            unsigned long long pa2 = pack2(a2, a2), pa3 = pack2(a3, a3);
            unsigned long long b01 = *reinterpret_cast<const unsigned long long*>(
                &Cs2[k * 34 + tx * 4]);
            unsigned long long b23 = *reinterpret_cast<const unsigned long long*>(
                &Cs2[k * 34 + tx * 4 + 2]);
            acc[0][0] = fma2(pa0, b01, acc[0][0]); acc[0][1] = fma2(pa0, b23, acc[0][1]);
            acc[1][0] = fma2(pa1, b01, acc[1][0]); acc[1][1] = fma2(pa1, b23, acc[1][1]);
            acc[2][0] = fma2(pa2, b01, acc[2][0]); acc[2][1] = fma2(pa2, b23, acc[2][1]);
            acc[3][0] = fma2(pa3, b01, acc[3][0]); acc[3][1] = fma2(pa3, b23, acc[3][1]);
        }
        if (ci < 6) {
            #pragma unroll
            for (int j = 0; j < 8; j++) As[(ci + 1) & 1][(sr + j * 16) * 17 + sk] = rg[j];
            __syncthreads();
        }
    }

    #pragma unroll
    for (int r = 0; r < 4; r++) {
        int row = i0 + ty * 4 + r;
        if (row >= M3) continue;
        float mt = meantex[row];
        #pragma unroll
        for (int p = 0; p < 2; p++) {
            float lo, hi;
            unpack2(acc[r][p], lo, hi);
            int b = tx * 4 + 2 * p;
            g_tex[(size_t)row * BATCH + b] = lo + mt;
            g_tex[(size_t)row * BATCH + b + 1] = hi + mt;
        }
    }
}

// ---------------------------------------------------------------------------
// Kernel C: face normals — warp per 2 faces. UNCHANGED (round 8).
// ---------------------------------------------------------------------------
__global__ __launch_bounds__(256) void facenorm_kernel(const int* __restrict__ face_buf) {
    int w = threadIdx.x >> 5;
    int lane = threadIdx.x & 31;
    int fbase = (blockIdx.x * 8 + w) * 2;
    #pragma unroll
    for (int u = 0; u < 2; u++) {
        int f = fbase + u;
        if (f > NF) continue;
        float4* dst = g_fnorm + (size_t)f * BATCH + lane;
        if (f == NF) { *dst = make_float4(0.f, 0.f, 0.f, 0.f); continue; }
        int i1 = face_buf[f * 3 + 0];
        int i2 = face_buf[f * 3 + 1];
        int i3 = face_buf[f * 3 + 2];
        float4 p1 = g_fs[(size_t)i1 * BATCH + lane];
        float4 p2 = g_fs[(size_t)i2 * BATCH + lane];
        float4 p3 = g_fs[(size_t)i3 * BATCH + lane];
        float e1x = __fsub_rn(p1.x, p2.x), e1y = __fsub_rn(p1.y, p2.y), e1z = __fsub_rn(p1.z, p2.z);
        float e2x = __fsub_rn(p2.x, p3.x), e2y = __fsub_rn(p2.y, p3.y), e2z = __fsub_rn(p2.z, p3.z);
        float cx = __fmaf_rn(e1y, e2z, -__fmul_rn(e1z, e2y));
        float cy = __fmaf_rn(e1z, e2x, -__fmul_rn(e1x, e2z));
        float cz = __fmaf_rn(e1x, e2y, -__fmul_rn(e1y, e2x));
        float n2 = __fadd_rn(__fadd_rn(__fmul_rn(cx, cx), __fmul_rn(cy, cy)), __fmul_rn(cz, cz));
        float len = sqrtf(n2);
        float d = fmaxf(len, 1e-12f);
        *dst = make_float4(__fdiv_rn(cx, d), __fdiv_rn(cy, d), __fdiv_rn(cz, d), 0.f);
    }
}

// ---------------------------------------------------------------------------
// Kernel D: vertex pass — warp per vertex, lane = batch. UNCHANGED (round 8).
// ---------------------------------------------------------------------------
__global__ __launch_bounds__(256) void vertex_kernel(
    const int* __restrict__ point_buf, const float* __restrict__ coeff,
    float* __restrict__ out) {
    __shared__ float srot[BATCH * 9];
    __shared__ float strans[BATCH * 3];
    __shared__ float sgsh[BATCH * 27];
    __shared__ float sfc[8 * BATCH * 3];
    __shared__ float sfst[8 * BATCH * 3];

    int t = threadIdx.x;
    for (int idx = t; idx < BATCH * 9; idx += 256) srot[idx] = g_rot[idx];
    for (int idx = t; idx < BATCH * 3; idx += 256)
        strans[idx] = coeff[(idx / 3) * 277 + 274 + (idx % 3)];
    for (int idx = t; idx < BATCH * 27; idx += 256) {
        int b = idx / 27, j = idx - b * 27;
        sgsh[idx] = coeff[b * 277 + 247 + j] + (((j % 9) == 0) ? 0.8f : 0.f);
    }
    __syncthreads();

    int w = t >> 5;
    int lane = t & 31;
    int v = blockIdx.x * 8 + w;

    if (v < NV) {
        const int4* pb = (const int4*)point_buf;
        int4 q0 = pb[(size_t)v * 2 + 0];
        int4 q1 = pb[(size_t)v * 2 + 1];
        const float4* fn = g_fnorm;
        float nx = 0.f, ny = 0.f, nz = 0.f;
        float4 a;
        a = fn[(size_t)q0.x * BATCH + lane]; nx += a.x; ny += a.y; nz += a.z;
        a = fn[(size_t)q0.y * BATCH + lane]; nx += a.x; ny += a.y; nz += a.z;
        a = fn[(size_t)q0.z * BATCH + lane]; nx += a.x; ny += a.y; nz += a.z;
        a = fn[(size_t)q0.w * BATCH + lane]; nx += a.x; ny += a.y; nz += a.z;
        a = fn[(size_t)q1.x * BATCH + lane]; nx += a.x; ny += a.y; nz += a.z;
        a = fn[(size_t)q1.y * BATCH + lane]; nx += a.x; ny += a.y; nz += a.z;
        a = fn[(size_t)q1.z * BATCH + lane]; nx += a.x; ny += a.y; nz += a.z;
        a = fn[(size_t)q1.w * BATCH + lane]; nx += a.x; ny += a.y; nz += a.z;

        float len = sqrtf(nx * nx + ny * ny + nz * nz);
        float inv = 1.f / fmaxf(len, 1e-12f);
        nx *= inv; ny *= inv; nz *= inv;

        const float* rot = srot + lane * 9;
        float rx = nx * rot[0] + ny * rot[3] + nz * rot[6];
        float ry = nx * rot[1] + ny * rot[4] + nz * rot[7];
        float rz = nx * rot[2] + ny * rot[5] + nz * rot[8];

        float Y[9];
        Y[0] = C_Y0;
        Y[1] = -C_Y1 * ry;
        Y[2] = C_Y1 * rz;
        Y[3] = -C_Y1 * rx;
        Y[4] = C_Y4 * rx * ry;
        Y[5] = -C_Y4 * ry * rz;
        Y[6] = C_Y6 * (3.f * rz * rz - 1.f);
        Y[7] = -C_Y4 * rx * rz;
        Y[8] = C_Y8 * (rx * rx - ry * ry);

        const float* gsh = sgsh + lane * 27;
        float lit[3];
        #pragma unroll
        for (int c = 0; c < 3; c++) {
            float s = 0.f;
            #pragma unroll
            for (int k = 0; k < 9; k++) s += Y[k] * gsh[c * 9 + k];
            lit[c] = s;
        }

        const float* texv = g_tex + (size_t)v * 3 * BATCH;
        float* fc = sfc + (w * BATCH + lane) * 3;
        fc[0] = texv[0 * BATCH + lane] * lit[0];
        fc[1] = texv[1 * BATCH + lane] * lit[1];
        fc[2] = texv[2 * BATCH + lane] * lit[2];

        float4 fs4 = g_fs[(size_t)v * BATCH + lane];
        const float* tr = strans + lane * 3;
        float* fo = sfst + (w * BATCH + lane) * 3;
        fo[0] = fs4.x * rot[0] + fs4.y * rot[3] + fs4.z * rot[6] + tr[0];
        fo[1] = fs4.x * rot[1] + fs4.y * rot[4] + fs4.z * rot[7] + tr[1];
        fo[2] = fs4.x * rot[2] + fs4.y * rot[5] + fs4.z * rot[8] + tr[2];
    }
    __syncthreads();

    size_t v0 = (size_t)blockIdx.x * 8;
    int b = t >> 3;
    int wv = t & 7;
    if (v0 + wv < NV) {
        #pragma unroll
        for (int c = 0; c < 3; c++) {
            size_t go = (size_t)b * NV3 + (v0 + wv) * 3 + c;
            out[OFF_FC + go] = sfc[(wv * BATCH + b) * 3 + c];
            out[OFF_FST + go] = sfst[(wv * BATCH + b) * 3 + c];
        }
    }
}

// ---------------------------------------------------------------------------
// Kernel E: landmarks in fp64 from raw inputs. UNCHANGED.
// ---------------------------------------------------------------------------
__global__ __launch_bounds__(128) void landmark_kernel(
    const float* __restrict__ idBase, const float* __restrict__ exBase,
    const float* __restrict__ meanshape, const float* __restrict__ coeff,
    const int* __restrict__ keypoints, float* __restrict__ out) {
    int idx = blockIdx.x * 128 + threadIdx.x;
    if (idx >= BATCH * 68) return;
    int b = idx / 68, l = idx - b * 68;
    int v = keypoints[l];
    const float* c = coeff + b * 277;

    double fs[3];
    #pragma unroll
    for (int cc = 0; cc < 3; cc++) {
        int row = 3 * v + cc;
        const float* idr = idBase + (size_t)row * 80;
        const float* exr = exBase + (size_t)row * 64;
        double s = 0.0;
        for (int k = 0; k < 80; k++) s += (double)idr[k] * (double)c[k];
        for (int k = 0; k < 64; k++) s += (double)exr[k] * (double)c[80 + k];
        fs[cc] = s + (double)meanshape[row] - g_mean_d[cc];
    }

    double ax0 = (double)c[244], ay0 = (double)c[245], az0 = (double)c[246];
    double cx = cos(ax0), sx = sin(ax0);
    double cy = cos(ay0), sy = sin(ay0);
    double cz = cos(az0), sz = sin(az0);
    double R[3][3];
    R[0][0] = cz * cy;  R[0][1] = cz * sy * sx - sz * cx;  R[0][2] = cz * sy * cx + sz * sx;
    R[1][0] = sz * cy;  R[1][1] = sz * sy * sx + cz * cx;  R[1][2] = sz * sy * cx - cz * sx;
    R[2][0] = -sy;      R[2][1] = cy * sx;                 R[2][2] = cy * cx;
    double fst[3];
    #pragma unroll
    for (int j = 0; j < 3; j++)
        fst[j] = fs[0] * R[j][0] + fs[1] * R[j][1] + fs[2] * R[j][2]
               + (double)c[274 + j];

    double Zc = 10.0 - fst[2];
    double lx = (1015.0 * fst[0] + 112.0 * Zc) / Zc;
    double ly = (1015.0 * fst[1] + 112.0 * Zc) / Zc;
    out[OFF_LM + (size_t)idx * 2 + 0] = (float)lx;
    out[OFF_LM + (size_t)idx * 2 + 1] = (float)ly;
}

// ---------------------------------------------------------------------------
// Launcher: fork-join stream overlap (round-8 topology).
// ---------------------------------------------------------------------------
extern "C" void kernel_launch(void* const* d_in, const int* in_sizes, int n_in,
                              void* d_out, int out_size) {
    const float* coeff     = (const float*)d_in[0];
    const float* idBase    = (const float*)d_in[1];
    const float* exBase    = (const float*)d_in[2];
    const float* texBase   = (const float*)d_in[3];
    const float* meanshape = (const float*)d_in[4];
    const float* meantex   = (const float*)d_in[5];
    const int*   face_buf  = (const int*)d_in[6];
    const int*   point_buf = (const int*)d_in[7];
    const int*   keypoints = (const int*)d_in[8];
    float* out = (float*)d_out;

    static cudaStream_t s2 = 0, s3 = 0;
    static cudaEvent_t evO = 0, evS = 0, evT = 0, evL = 0;
    if (!s2) {
        cudaStreamCreateWithFlags(&s2, cudaStreamNonBlocking);
        cudaStreamCreateWithFlags(&s3, cudaStreamNonBlocking);
        cudaEventCreateWithFlags(&evO, cudaEventDisableTiming);
        cudaEventCreateWithFlags(&evS, cudaEventDisableTiming);
        cudaEventCreateWithFlags(&evT, cudaEventDisableTiming);
        cudaEventCreateWithFlags(&evL, cudaEventDisableTiming);
    }

    int gemm_blocks = (M3 + 127) / 128;

    cudaEventRecord(evO, 0);
    cudaStreamWaitEvent(s2, evO, 0);
    cudaStreamWaitEvent(s3, evO, 0);

    gemm_tex_kernel<<<gemm_blocks, 256, 0, s2>>>(texBase, coeff, meantex);
    cudaEventRecord(evT, s2);

    setup_kernel<<<1, 1024>>>(coeff, meanshape);
    cudaEventRecord(evS, 0);
    gemm_fs_kernel<<<gemm_blocks, 256>>>(idBase, exBase, coeff, meanshape);
    facenorm_kernel<<<(NFP1 + 15) / 16, 256>>>(face_buf);

    cudaStreamWaitEvent(s3, evS, 0);
    landmark_kernel<<<(BATCH * 68 + 127) / 128, 128, 0, s3>>>(
        idBase, exBase, meanshape, coeff, keypoints, out);
    cudaEventRecord(evL, s3);

    cudaStreamWaitEvent(0, evT, 0);
    vertex_kernel<<<(NV + 7) / 8, 256>>>(point_buf, coeff, out);
    cudaStreamWaitEvent(0, evL, 0);
}